// round 7
// baseline (speedup 1.0000x reference)
#include <cuda_runtime.h>
#include <cuda_bf16.h>
#include <cuda_fp8.h>
#include <math.h>
#include <stdint.h>

// Problem constants
#define NROWS 16384
#define NE    16384
#define D     256
#define HW    1024
#define CHW   262144

#define NT       128        // number of 128-code tiles
#define MARGIN_Y 6e-3f
#define CAP      64
#define ESCALE   4194304.0f          // 2^22
#define MSCALE   (-4.76837158203125e-07f)  // -2 * 2^-22 = -2^-21 (exact)

// Output layout (concatenated reference tuple, float32)
#define ZQ_OFF   0ULL
#define LOSS_OFF 4194304ULL
#define PERP_OFF 4194305ULL
#define OH_OFF   4194306ULL
#define IDX_OFF  272629762ULL

// Scratch
__device__ float  g_enorm[NE];
__device__ float  g_enoff[NE];       // fl(E + 0.0625)
__device__ float  g_znorm[NROWS];
__device__ int    g_idx[NROWS];
__device__ int    g_count[NE];
__device__ double g_losspart[16384];
__device__ uint32_t g_e8[NE * D / 4];  // fp8 codebook (scaled by 2^22)
__device__ float  g_candv[NROWS * CAP];
__device__ int    g_candi[NROWS * CAP];
__device__ float  g_bv[NROWS];
__device__ int    g_candn[NROWS];

// ---------------------------------------------------------------------------
// Baseline-PTX helpers
// ---------------------------------------------------------------------------
__device__ __forceinline__ uint32_t smem_to_u32(const void* p) {
    uint32_t a;
    asm("{ .reg .u64 t; cvta.to.shared.u64 t, %1; cvt.u32.u64 %0, t; }" : "=r"(a) : "l"(p));
    return a;
}
__device__ __forceinline__ void cp_async16(uint32_t sa, const void* g) {
    asm volatile("cp.async.cg.shared.global [%0], [%1], 16;" :: "r"(sa), "l"(g));
}
#define CP_COMMIT() asm volatile("cp.async.commit_group;" ::: "memory")
#define CP_WAIT(n)  asm volatile("cp.async.wait_group %0;" :: "n"(n) : "memory")

__device__ __forceinline__ void ldm_x4(uint32_t* r, uint32_t addr) {
    asm volatile("ldmatrix.sync.aligned.m8n8.x4.shared.b16 {%0,%1,%2,%3}, [%4];"
                 : "=r"(r[0]), "=r"(r[1]), "=r"(r[2]), "=r"(r[3]) : "r"(addr));
}
__device__ __forceinline__ void mma16832(float* c, const uint32_t* a, uint32_t b0, uint32_t b1) {
    asm volatile("mma.sync.aligned.m16n8k32.row.col.f32.e4m3.e4m3.f32 "
                 "{%0,%1,%2,%3}, {%4,%5,%6,%7}, {%8,%9}, {%0,%1,%2,%3};"
                 : "+f"(c[0]), "+f"(c[1]), "+f"(c[2]), "+f"(c[3])
                 : "r"(a[0]), "r"(a[1]), "r"(a[2]), "r"(a[3]), "r"(b0), "r"(b1));
}
// pack 4 floats -> 4 e4m3 bytes (memory order v0,v1,v2,v3)
__device__ __forceinline__ uint32_t pack_e4m3x4(float v0, float v1, float v2, float v3) {
    uint16_t lo, hi;
    asm("cvt.rn.satfinite.e4m3x2.f32 %0, %1, %2;" : "=h"(lo) : "f"(v1), "f"(v0));
    asm("cvt.rn.satfinite.e4m3x2.f32 %0, %1, %2;" : "=h"(hi) : "f"(v3), "f"(v2));
    return (uint32_t)lo | ((uint32_t)hi << 16);
}

// ---------------------------------------------------------------------------
// Zero-fill (runs on side stream, overlapped with k_main)
// ---------------------------------------------------------------------------
__global__ void k_zero(float* __restrict__ out, long long total) {
    float4* o4 = (float4*)(out + LOSS_OFF);
    long long n = total - (long long)LOSS_OFF;
    long long n4 = n / 4;
    long long i = (long long)blockIdx.x * blockDim.x + threadIdx.x;
    long long stride = (long long)gridDim.x * blockDim.x;
    float4 zz = make_float4(0.f, 0.f, 0.f, 0.f);
    for (long long p = i; p < n4; p += stride) o4[p] = zz;
    long long t0 = n4 * 4;
    if (i < n - t0) out[LOSS_OFF + t0 + i] = 0.f;
}

__global__ void k_zero_counts() {
    int i = blockIdx.x * blockDim.x + threadIdx.x;
    if (i < NE) g_count[i] = 0;
}

// ---------------------------------------------------------------------------
// Fused: ||e||^2 (strict sequential fp32), E+offset, fp8(e * 2^22)
// 512 blocks x 256 threads, 32 rows per block.
// ---------------------------------------------------------------------------
__global__ void k_eprep(const float* __restrict__ emb) {
    __shared__ float se[32 * 257];
    int r0 = blockIdx.x * 32;
    int tid = threadIdx.x;
    const float* src = emb + (size_t)r0 * D;
    #pragma unroll
    for (int l = 0; l < 32; l++) {
        int i = l * 256 + tid;          // 8192 elements
        int r = i >> 8, c = i & 255;
        se[r * 257 + c] = src[i];
    }
    __syncthreads();
    // fp8 conversion: 2048 u32 outputs
    #pragma unroll
    for (int l = 0; l < 8; l++) {
        int id = l * 256 + tid;         // u32 index
        int r = id >> 6, c4 = (id & 63) * 4;
        float v0 = se[r * 257 + c4]     * ESCALE;
        float v1 = se[r * 257 + c4 + 1] * ESCALE;
        float v2 = se[r * 257 + c4 + 2] * ESCALE;
        float v3 = se[r * 257 + c4 + 3] * ESCALE;
        g_e8[(size_t)(r0 + r) * 64 + (id & 63)] = pack_e4m3x4(v0, v1, v2, v3);
    }
    if (tid < 32) {
        float s = 0.f;
        const float* row = se + tid * 257;
        for (int k = 0; k < D; k++) s = __fadd_rn(s, __fmul_rn(row[k], row[k]));
        g_enorm[r0 + tid] = s;
        g_enoff[r0 + tid] = __fadd_rn(s, 0.0625f);
    }
}

__global__ void k_znorm(const float* __restrict__ z) {
    int r = blockIdx.x * blockDim.x + threadIdx.x;
    if (r >= NROWS) return;
    int b = r >> 10, hw = r & 1023;
    const float* base = z + (size_t)b * CHW + hw;
    float s = 0.f;
    for (int c = 0; c < D; c++) { float v = base[(size_t)c * HW]; s = __fadd_rn(s, __fmul_rn(v, v)); }
    g_znorm[r] = s;
}

// ---------------------------------------------------------------------------
// Main fp8 mma.sync GEMM, two passes over tiles (pass0 min, pass1 append).
// y(j) = (E_j + 1/16) - 2*m_hat(j)  > 0 always.
// ---------------------------------------------------------------------------
#define PITCH 272
#define A_OFF 0
#define A_SZ  (128 * PITCH)             // 34816
#define B_OFF A_SZ
#define B_SZ  (128 * PITCH)             // per buffer
#define EN_OFF (B_OFF + 2 * B_SZ)       // 104448
#define BV_OFF (EN_OFF + 1024)          // 105472
#define CN_OFF (BV_OFF + 512)           // 105984
#define SMEM_BYTES (CN_OFF + 512)       // 106496

__device__ __forceinline__ void load_btile(uint32_t sB, int j0, int tid) {
    #pragma unroll
    for (int l = 0; l < 8; l++) {
        int cid = l * 256 + tid;        // 2048 16B chunks
        int n   = cid >> 4;
        int c16 = cid & 15;
        cp_async16(sB + (uint32_t)n * PITCH + (uint32_t)c16 * 16,
                   (const char*)g_e8 + ((size_t)(j0 + n) << 8) + c16 * 16);
    }
}

__device__ __forceinline__ void compute_tile(uint32_t sbase, int buf, int wm, int wn,
                                             int lane, float acc[4][4][4]) {
    #pragma unroll
    for (int mt = 0; mt < 4; mt++)
        #pragma unroll
        for (int nt = 0; nt < 4; nt++)
            #pragma unroll
            for (int rr = 0; rr < 4; rr++) acc[mt][nt][rr] = 0.f;

    uint32_t aBase = sbase + A_OFF + (uint32_t)(wm * 64 + (lane & 15)) * PITCH + (uint32_t)(lane >> 4) * 16;
    uint32_t bBase = sbase + B_OFF + (uint32_t)buf * B_SZ
                   + (uint32_t)(wn * 32 + (lane & 15)) * PITCH + (uint32_t)(lane >> 4) * 16;

    #pragma unroll
    for (int ks = 0; ks < 8; ks++) {     // 8 x k32 = 256
        uint32_t ra[4][4], rb[2][4];
        #pragma unroll
        for (int mt = 0; mt < 4; mt++)
            ldm_x4(ra[mt], aBase + (uint32_t)mt * (16 * PITCH) + (uint32_t)ks * 32);
        #pragma unroll
        for (int np = 0; np < 2; np++)
            ldm_x4(rb[np], bBase + (uint32_t)np * (16 * PITCH) + (uint32_t)ks * 32);
        #pragma unroll
        for (int mt = 0; mt < 4; mt++) {
            mma16832(acc[mt][0], ra[mt], rb[0][0], rb[0][2]);
            mma16832(acc[mt][1], ra[mt], rb[0][1], rb[0][3]);
            mma16832(acc[mt][2], ra[mt], rb[1][0], rb[1][2]);
            mma16832(acc[mt][3], ra[mt], rb[1][1], rb[1][3]);
        }
    }
}

__launch_bounds__(256, 1)
__global__ void k_main(const float* __restrict__ z) {
    extern __shared__ char smem[];
    uint32_t sbase = smem_to_u32(smem);
    float* enf  = (float*)(smem + EN_OFF);
    int*   sbv  = (int*)(smem + BV_OFF);
    int*   scnt = (int*)(smem + CN_OFF);

    int tid  = threadIdx.x;
    int lane = tid & 31;
    int wid  = tid >> 5;
    int wm = wid >> 2;      // 0..1
    int wn = wid & 3;       // 0..3
    int row0 = blockIdx.x * 128;
    int b0 = row0 >> 10;
    int hw0 = row0 & 1023;

    // ---- Stage A: z -> fp8 smem [m][k] ----
    {
        const float* zb = z + (size_t)b0 * CHW + hw0;
        int m = tid & 127;
        int chalf = (tid >> 7) * 128;
        #pragma unroll 4
        for (int cc = 0; cc < 32; cc++) {
            int c = chalf + cc * 4;
            float v0 = zb[(size_t)c * HW + m];
            float v1 = zb[(size_t)(c + 1) * HW + m];
            float v2 = zb[(size_t)(c + 2) * HW + m];
            float v3 = zb[(size_t)(c + 3) * HW + m];
            *(uint32_t*)(smem + A_OFF + m * PITCH + c) = pack_e4m3x4(v0, v1, v2, v3);
        }
    }
    if (tid < 128) {
        sbv[tid] = 0x7f800000;          // +inf
        scnt[tid] = 0;
    }
    load_btile(sbase + B_OFF, 0, tid);
    if (tid < 32) cp_async16(sbase + EN_OFF + tid * 16, g_enoff + tid * 4);
    CP_COMMIT();

    // =========================== PASS 0: min only ===========================
    float bvloc[4][2];
    #pragma unroll
    for (int mt = 0; mt < 4; mt++) { bvloc[mt][0] = INFINITY; bvloc[mt][1] = INFINITY; }

    #pragma unroll 1
    for (int t = 0; t < NT; t++) {
        __syncthreads();
        int buf = t & 1;
        if (t + 1 < NT) {
            load_btile(sbase + B_OFF + (uint32_t)(buf ^ 1) * B_SZ, (t + 1) * 128, tid);
            if (tid < 32) cp_async16(sbase + EN_OFF + (uint32_t)(buf ^ 1) * 512 + tid * 16,
                                     g_enoff + (t + 1) * 128 + tid * 4);
            CP_COMMIT();
            CP_WAIT(1);
        } else {
            CP_WAIT(0);
        }
        __syncthreads();

        float acc[4][4][4];
        compute_tile(sbase, buf, wm, wn, lane, acc);

        const float* enb = enf + buf * 128;
        #pragma unroll
        for (int mt = 0; mt < 4; mt++) {
            float b0v = bvloc[mt][0], b1v = bvloc[mt][1];
            #pragma unroll
            for (int nt = 0; nt < 4; nt++) {
                int cl = wn * 32 + nt * 8 + (lane & 3) * 2;
                float E0 = enb[cl], E1 = enb[cl + 1];
                float y00 = fmaf(acc[mt][nt][0], MSCALE, E0);
                float y01 = fmaf(acc[mt][nt][1], MSCALE, E1);
                float y10 = fmaf(acc[mt][nt][2], MSCALE, E0);
                float y11 = fmaf(acc[mt][nt][3], MSCALE, E1);
                b0v = fminf(b0v, fminf(y00, y01));
                b1v = fminf(b1v, fminf(y10, y11));
            }
            bvloc[mt][0] = b0v; bvloc[mt][1] = b1v;
        }
    }
    #pragma unroll
    for (int mt = 0; mt < 4; mt++) {
        int r0 = wm * 64 + mt * 16 + (lane >> 2);
        atomicMin(&sbv[r0],     __float_as_int(bvloc[mt][0]));   // y > 0 always
        atomicMin(&sbv[r0 + 8], __float_as_int(bvloc[mt][1]));
    }
    __syncthreads();

    float thr[4][2];
    #pragma unroll
    for (int mt = 0; mt < 4; mt++) {
        int r0 = wm * 64 + mt * 16 + (lane >> 2);
        thr[mt][0] = __int_as_float(sbv[r0]) + MARGIN_Y;
        thr[mt][1] = __int_as_float(sbv[r0 + 8]) + MARGIN_Y;
    }

    // reload tile 0 for pass 1
    load_btile(sbase + B_OFF, 0, tid);
    if (tid < 32) cp_async16(sbase + EN_OFF + tid * 16, g_enoff + tid * 4);
    CP_COMMIT();

    // ====================== PASS 1: append below threshold ==================
    #pragma unroll 1
    for (int t = 0; t < NT; t++) {
        __syncthreads();
        int buf = t & 1;
        if (t + 1 < NT) {
            load_btile(sbase + B_OFF + (uint32_t)(buf ^ 1) * B_SZ, (t + 1) * 128, tid);
            if (tid < 32) cp_async16(sbase + EN_OFF + (uint32_t)(buf ^ 1) * 512 + tid * 16,
                                     g_enoff + (t + 1) * 128 + tid * 4);
            CP_COMMIT();
            CP_WAIT(1);
        } else {
            CP_WAIT(0);
        }
        __syncthreads();

        float acc[4][4][4];
        compute_tile(sbase, buf, wm, wn, lane, acc);

        int j0 = t * 128;
        const float* enb = enf + buf * 128;
        #pragma unroll
        for (int mt = 0; mt < 4; mt++) {
            int r0 = wm * 64 + mt * 16 + (lane >> 2);
            int r1 = r0 + 8;
            float t0 = thr[mt][0], t1 = thr[mt][1];
            #pragma unroll
            for (int nt = 0; nt < 4; nt++) {
                int cl = wn * 32 + nt * 8 + (lane & 3) * 2;
                float E0 = enb[cl], E1 = enb[cl + 1];
                #pragma unroll
                for (int e = 0; e < 2; e++) {
                    float Ee = e ? E1 : E0;
                    int   jj = j0 + cl + e;
                    float y0 = fmaf(acc[mt][nt][e],     MSCALE, Ee);
                    float y1 = fmaf(acc[mt][nt][2 + e], MSCALE, Ee);
                    if (y0 < t0) {
                        int pos = atomicAdd(&scnt[r0], 1);
                        if (pos < CAP) {
                            g_candv[(size_t)(row0 + r0) * CAP + pos] = y0;
                            g_candi[(size_t)(row0 + r0) * CAP + pos] = jj;
                        }
                    }
                    if (y1 < t1) {
                        int pos = atomicAdd(&scnt[r1], 1);
                        if (pos < CAP) {
                            g_candv[(size_t)(row0 + r1) * CAP + pos] = y1;
                            g_candi[(size_t)(row0 + r1) * CAP + pos] = jj;
                        }
                    }
                }
            }
        }
    }
    __syncthreads();
    if (tid < 128) {
        g_bv[row0 + tid] = __int_as_float(sbv[tid]);
        g_candn[row0 + tid] = scnt[tid];
    }
}

// ---------------------------------------------------------------------------
// Exact rescore: one warp per row, bit-exact sequential fp32 chain.
// ---------------------------------------------------------------------------
__global__ void k_rescore(const float* __restrict__ z, const float* __restrict__ emb) {
    int w = (blockIdx.x * blockDim.x + threadIdx.x) >> 5;
    int lane = threadIdx.x & 31;
    if (w >= NROWS) return;
    int n = g_candn[w];
    if (n > CAP) return;                     // overflow -> fallback kernel
    float thr = g_bv[w] + MARGIN_Y;

    float v = INFINITY; int idx = 0x7fffffff;
    int b = w >> 10, hw = w & 1023;
    const float* zr = z + (size_t)b * CHW + hw;
    float Sz = g_znorm[w];

    #pragma unroll
    for (int s = 0; s < 2; s++) {
        int slot = lane + s * 32;
        bool act = (slot < n) && (g_candv[(size_t)w * CAP + slot] < thr);
        if (act) {
            int ci = g_candi[(size_t)w * CAP + slot];
            const float* er = emb + (size_t)ci * D;
            float a = 0.f;
            for (int c = 0; c < D; c++) a = fmaf(zr[(size_t)c * HW], er[c], a);
            float dd = __fadd_rn(__fadd_rn(Sz, g_enorm[ci]), __fmul_rn(-2.0f, a));
            if (dd < v || (dd == v && ci < idx)) { v = dd; idx = ci; }
        }
    }
    #pragma unroll
    for (int o = 16; o; o >>= 1) {
        float vo = __shfl_xor_sync(0xffffffffu, v, o);
        int io = __shfl_xor_sync(0xffffffffu, idx, o);
        if (vo < v || (vo == v && io < idx)) { v = vo; idx = io; }
    }
    if (lane == 0) g_idx[w] = idx;
}

// Fallback: full exact scan for overflowed rows (expected: none).
__global__ void k_fallback(const float* __restrict__ z, const float* __restrict__ emb) {
    int row = blockIdx.x;
    if (g_candn[row] <= CAP) return;
    __shared__ float zrow[256];
    __shared__ float sv[256];
    __shared__ int si[256];
    int b = row >> 10, hw = row & 1023;
    const float* zr = z + (size_t)b * CHW + hw;
    zrow[threadIdx.x] = zr[(size_t)threadIdx.x * HW];
    __syncthreads();
    float S = g_znorm[row];
    float bvv = INFINITY; int bi = 0x7fffffff;
    for (int j = threadIdx.x; j < NE; j += 256) {
        const float* er = emb + (size_t)j * D;
        float acc = 0.f;
        for (int c = 0; c < D; c++) acc = fmaf(zrow[c], er[c], acc);
        float dd = __fadd_rn(__fadd_rn(S, g_enorm[j]), __fmul_rn(-2.0f, acc));
        if (dd < bvv) { bvv = dd; bi = j; }
    }
    sv[threadIdx.x] = bvv; si[threadIdx.x] = bi;
    __syncthreads();
    for (int s = 128; s; s >>= 1) {
        if (threadIdx.x < s) {
            if (sv[threadIdx.x + s] < sv[threadIdx.x] ||
                (sv[threadIdx.x + s] == sv[threadIdx.x] && si[threadIdx.x + s] < si[threadIdx.x])) {
                sv[threadIdx.x] = sv[threadIdx.x + s]; si[threadIdx.x] = si[threadIdx.x + s];
            }
        }
        __syncthreads();
    }
    if (threadIdx.x == 0) g_idx[row] = si[0];
}

// ---------------------------------------------------------------------------
__global__ void k_finalize(float* __restrict__ out) {
    int r = blockIdx.x * blockDim.x + threadIdx.x;
    if (r >= NROWS) return;
    int idx = g_idx[r];
    out[IDX_OFF + r] = (float)idx;
    out[OH_OFF + (size_t)r * NE + idx] = 1.0f;
    atomicAdd(&g_count[idx], 1);
}

__global__ void k_zq_loss(const float* __restrict__ z, const float* __restrict__ emb,
                          float* __restrict__ out) {
    int t = blockIdx.x * 256 + threadIdx.x;
    int bi = t >> 18;
    int c  = (t >> 10) & 255;
    int hw = t & 1023;
    int row = (bi << 10) + hw;
    int idx = g_idx[row];
    float e  = emb[(size_t)idx * D + c];
    float zp = z[t];
    float diff = __fadd_rn(e, -zp);
    out[ZQ_OFF + (size_t)t] = __fadd_rn(zp, diff);
    __shared__ double sd[256];
    sd[threadIdx.x] = (double)diff * (double)diff;
    __syncthreads();
    #pragma unroll
    for (int s = 128; s > 0; s >>= 1) {
        if (threadIdx.x < s) sd[threadIdx.x] += sd[threadIdx.x + s];
        __syncthreads();
    }
    if (threadIdx.x == 0) g_losspart[blockIdx.x] = sd[0];
}

__global__ void k_loss_final(float* __restrict__ out) {
    __shared__ double sd[1024];
    double s = 0.0;
    for (int i = threadIdx.x; i < 16384; i += 1024) s += g_losspart[i];
    sd[threadIdx.x] = s;
    __syncthreads();
    #pragma unroll
    for (int st = 512; st > 0; st >>= 1) {
        if (threadIdx.x < st) sd[threadIdx.x] += sd[threadIdx.x + st];
        __syncthreads();
    }
    if (threadIdx.x == 0) {
        float m = (float)(sd[0] / 4194304.0);
        out[LOSS_OFF] = __fadd_rn(m, __fmul_rn(0.25f, m));
    }
}

__global__ void k_perp(float* __restrict__ out) {
    __shared__ double sd[1024];
    double s = 0.0;
    for (int j = threadIdx.x; j < NE; j += 1024) {
        float p = (float)g_count[j] * (1.0f / 16384.0f);
        double pd = (double)p;
        s += pd * log(pd + 1e-10);
    }
    sd[threadIdx.x] = s;
    __syncthreads();
    #pragma unroll
    for (int st = 512; st > 0; st >>= 1) {
        if (threadIdx.x < st) sd[threadIdx.x] += sd[threadIdx.x + st];
        __syncthreads();
    }
    if (threadIdx.x == 0) out[PERP_OFF] = (float)exp(-sd[0]);
}

// ---------------------------------------------------------------------------
extern "C" void kernel_launch(void* const* d_in, const int* in_sizes, int n_in,
                              void* d_out, int out_size) {
    const float* z   = (const float*)d_in[0];
    const float* emb = (const float*)d_in[1];
    float* out = (float*)d_out;

    static cudaStream_t s2 = nullptr;
    static cudaEvent_t evF = nullptr, evJ = nullptr;
    if (!s2) {
        cudaFuncSetAttribute(k_main, cudaFuncAttributeMaxDynamicSharedMemorySize, SMEM_BYTES);
        cudaStreamCreateWithFlags(&s2, cudaStreamNonBlocking);
        cudaEventCreateWithFlags(&evF, cudaEventDisableTiming);
        cudaEventCreateWithFlags(&evJ, cudaEventDisableTiming);
    }

    // Fork: zero-fill (1.07 GB) runs concurrently with the GEMM pipeline.
    cudaEventRecord(evF, 0);
    cudaStreamWaitEvent(s2, evF, 0);
    k_zero<<<8192, 256, 0, s2>>>(out, (long long)out_size);
    k_zero_counts<<<64, 256, 0, s2>>>();
    cudaEventRecord(evJ, s2);

    k_eprep<<<NE / 32, 256>>>(emb);
    k_znorm<<<NROWS / 256, 256>>>(z);

    k_main<<<128, 256, SMEM_BYTES>>>(z);

    k_rescore<<<NROWS / 8, 256>>>(z, emb);
    k_fallback<<<NROWS, 256>>>(z, emb);

    cudaStreamWaitEvent(0, evJ, 0);     // join before touching out[OH..]
    k_finalize<<<NROWS / 256, 256>>>(out);
    k_zq_loss<<<(NROWS * D) / 256, 256>>>(z, emb, out);
    k_loss_final<<<1, 1024>>>(out);
    k_perp<<<1, 1024>>>(out);
}

// round 8
// speedup vs baseline: 74.3527x; 74.3527x over previous
#include <cuda_runtime.h>
#include <cuda_bf16.h>
#include <math.h>
#include <stdint.h>

// Problem constants
#define NROWS 16384
#define NE    16384
#define D     256
#define HW    1024
#define CHW   262144

#define NT       128        // number of 128-code tiles
#define MARGIN_M 2e-4f      // margin on m_hat (d-margin 4e-4, validated R6)

// Output layout (concatenated reference tuple, float32)
#define ZQ_OFF   0ULL
#define LOSS_OFF 4194304ULL
#define PERP_OFF 4194305ULL
#define OH_OFF   4194306ULL
#define IDX_OFF  272629762ULL

// Scratch
__device__ float  g_enorm[NE];
__device__ float  g_znorm[NROWS];
__device__ int    g_idx[NROWS];
__device__ int    g_count[NE];
__device__ double g_losspart[16384];
__device__ unsigned short g_ebf[NE * D];       // bf16 codebook
__device__ float  g_smin[(size_t)NROWS * 512]; // per-row per-32-code-subtile max(m_hat)

// ---------------------------------------------------------------------------
// Baseline-PTX helpers
// ---------------------------------------------------------------------------
__device__ __forceinline__ uint32_t smem_to_u32(const void* p) {
    uint32_t a;
    asm("{ .reg .u64 t; cvta.to.shared.u64 t, %1; cvt.u32.u64 %0, t; }" : "=r"(a) : "l"(p));
    return a;
}
__device__ __forceinline__ void cp_async16(uint32_t sa, const void* g) {
    asm volatile("cp.async.cg.shared.global [%0], [%1], 16;" :: "r"(sa), "l"(g));
}
#define CP_COMMIT() asm volatile("cp.async.commit_group;" ::: "memory")
#define CP_WAIT(n)  asm volatile("cp.async.wait_group %0;" :: "n"(n) : "memory")

__device__ __forceinline__ void ldm_x4(uint32_t* r, uint32_t addr) {
    asm volatile("ldmatrix.sync.aligned.m8n8.x4.shared.b16 {%0,%1,%2,%3}, [%4];"
                 : "=r"(r[0]), "=r"(r[1]), "=r"(r[2]), "=r"(r[3]) : "r"(addr));
}
__device__ __forceinline__ void mma16816(float* c, const uint32_t* a, uint32_t b0, uint32_t b1) {
    asm volatile("mma.sync.aligned.m16n8k16.row.col.f32.bf16.bf16.f32 "
                 "{%0,%1,%2,%3}, {%4,%5,%6,%7}, {%8,%9}, {%0,%1,%2,%3};"
                 : "+f"(c[0]), "+f"(c[1]), "+f"(c[2]), "+f"(c[3])
                 : "r"(a[0]), "r"(a[1]), "r"(a[2]), "r"(a[3]), "r"(b0), "r"(b1));
}

// ---------------------------------------------------------------------------
// Zero-fill (side stream, overlapped with GEMM)
// ---------------------------------------------------------------------------
__global__ void k_zero(float* __restrict__ out, long long total) {
    float4* o4 = (float4*)(out + LOSS_OFF);
    long long n = total - (long long)LOSS_OFF;
    long long n4 = n / 4;
    long long i = (long long)blockIdx.x * blockDim.x + threadIdx.x;
    long long stride = (long long)gridDim.x * blockDim.x;
    float4 zz = make_float4(0.f, 0.f, 0.f, 0.f);
    for (long long p = i; p < n4; p += stride) o4[p] = zz;
    long long t0 = n4 * 4;
    if (i < n - t0) out[LOSS_OFF + t0 + i] = 0.f;
}

__global__ void k_zero_counts() {
    int i = blockIdx.x * blockDim.x + threadIdx.x;
    if (i < NE) g_count[i] = 0;
}

// ---------------------------------------------------------------------------
// Fused e-prep: bf16 codebook + exact sequential ||e||^2
// 512 blocks x 256 threads, 32 rows per block.
// ---------------------------------------------------------------------------
__global__ void k_eprep(const float* __restrict__ emb) {
    __shared__ float se[32 * 257];
    int r0 = blockIdx.x * 32;
    int tid = threadIdx.x;
    const float* src = emb + (size_t)r0 * D;
    #pragma unroll
    for (int l = 0; l < 32; l++) {
        int i = l * 256 + tid;
        se[(i >> 8) * 257 + (i & 255)] = src[i];
    }
    __syncthreads();
    #pragma unroll
    for (int l = 0; l < 16; l++) {
        int id = l * 256 + tid;              // u32 out index (4096 per block)
        int r = id >> 7, c2 = (id & 127) * 2;
        __nv_bfloat16 h0 = __float2bfloat16_rn(se[r * 257 + c2]);
        __nv_bfloat16 h1 = __float2bfloat16_rn(se[r * 257 + c2 + 1]);
        uint32_t w = (uint32_t)*(unsigned short*)&h0 | ((uint32_t)*(unsigned short*)&h1 << 16);
        ((uint32_t*)g_ebf)[(size_t)(r0 + r) * 128 + (id & 127)] = w;
    }
    if (tid < 32) {
        float s = 0.f;
        const float* row = se + tid * 257;
        for (int k = 0; k < D; k++) s = __fadd_rn(s, __fmul_rn(row[k], row[k]));
        g_enorm[r0 + tid] = s;
    }
}

__global__ void k_znorm(const float* __restrict__ z) {
    int r = blockIdx.x * blockDim.x + threadIdx.x;
    if (r >= NROWS) return;
    int b = r >> 10, hw = r & 1023;
    const float* base = z + (size_t)b * CHW + hw;
    float s = 0.f;
    for (int c = 0; c < D; c++) { float v = base[(size_t)c * HW]; s = __fadd_rn(s, __fmul_rn(v, v)); }
    g_znorm[r] = s;
}

// ---------------------------------------------------------------------------
// Main bf16 mma.sync GEMM — SINGLE pass; writes per-(row, 32-code subtile)
// max of m_hat to g_smin. 128 CTAs x 256 threads (8 warps, 2x4).
// ---------------------------------------------------------------------------
#define PITCH 528
#define A_OFF 0
#define B_OFF 67584
#define B_SZ  67584
#define ST_OFF (B_OFF + 2 * B_SZ)           // 202752: stmin[4][128] floats
#define SMEM_BYTES (ST_OFF + 2048)          // 204800

__device__ __forceinline__ void load_btile(uint32_t sB, int j0, int tid) {
    #pragma unroll
    for (int l = 0; l < 16; l++) {
        int cid = l * 256 + tid;            // 4096 16B chunks
        int n   = cid >> 5;
        int c16 = cid & 31;
        cp_async16(sB + (uint32_t)n * PITCH + (uint32_t)c16 * 16,
                   g_ebf + ((size_t)(j0 + n) << 8) + c16 * 8);
    }
}

__launch_bounds__(256, 1)
__global__ void k_main(const float* __restrict__ z) {
    extern __shared__ char smem[];
    uint32_t sbase = smem_to_u32(smem);
    float* stmin = (float*)(smem + ST_OFF);   // [wn][row] subtile max

    int tid  = threadIdx.x;
    int lane = tid & 31;
    int wid  = tid >> 5;
    int wm = wid >> 2;      // 0..1
    int wn = wid & 3;       // 0..3
    int row0 = blockIdx.x * 128;
    int b0 = row0 >> 10;
    int hw0 = row0 & 1023;

    // ---- Stage A: z -> bf16 smem [m][k], pitch 528 ----
    {
        const float* zb = z + (size_t)b0 * CHW + hw0;
        int m = tid & 127;
        int chalf = (tid >> 7) * 128;
        #pragma unroll 4
        for (int cc = 0; cc < 64; cc++) {
            int c = chalf + cc * 2;
            float v0 = zb[(size_t)c * HW + m];
            float v1 = zb[(size_t)(c + 1) * HW + m];
            __nv_bfloat16 h0 = __float2bfloat16_rn(v0);
            __nv_bfloat16 h1 = __float2bfloat16_rn(v1);
            uint32_t w = (uint32_t)*(unsigned short*)&h0 | ((uint32_t)*(unsigned short*)&h1 << 16);
            *(uint32_t*)(smem + A_OFF + m * PITCH + c * 2) = w;
        }
    }
    load_btile(sbase + B_OFF, 0, tid);
    CP_COMMIT();

    #pragma unroll 1
    for (int t = 0; t < NT; t++) {
        __syncthreads();                     // buf^1 free; stmin consumed
        int buf = t & 1;
        if (t + 1 < NT) {
            load_btile(sbase + B_OFF + (uint32_t)(buf ^ 1) * B_SZ, (t + 1) * 128, tid);
            CP_COMMIT();
            CP_WAIT(1);
        } else {
            CP_WAIT(0);
        }
        __syncthreads();                     // tile t visible

        // ---- 16 k-steps of mma ----
        float acc[4][4][4];
        #pragma unroll
        for (int mt = 0; mt < 4; mt++)
            #pragma unroll
            for (int nt = 0; nt < 4; nt++)
                #pragma unroll
                for (int rr = 0; rr < 4; rr++) acc[mt][nt][rr] = 0.f;

        uint32_t aBase = sbase + A_OFF + (uint32_t)(wm * 64 + (lane & 15)) * PITCH + (uint32_t)(lane >> 4) * 16;
        uint32_t bBase = sbase + B_OFF + (uint32_t)buf * B_SZ
                       + (uint32_t)(wn * 32 + (lane & 15)) * PITCH + (uint32_t)(lane >> 4) * 16;

        #pragma unroll
        for (int ks = 0; ks < 16; ks++) {
            uint32_t ra[4][4], rb[2][4];
            #pragma unroll
            for (int mt = 0; mt < 4; mt++)
                ldm_x4(ra[mt], aBase + (uint32_t)mt * (16 * PITCH) + (uint32_t)ks * 32);
            #pragma unroll
            for (int np = 0; np < 2; np++)
                ldm_x4(rb[np], bBase + (uint32_t)np * (16 * PITCH) + (uint32_t)ks * 32);
            #pragma unroll
            for (int mt = 0; mt < 4; mt++) {
                mma16816(acc[mt][0], ra[mt], rb[0][0], rb[0][2]);
                mma16816(acc[mt][1], ra[mt], rb[0][1], rb[0][3]);
                mma16816(acc[mt][2], ra[mt], rb[1][0], rb[1][2]);
                mma16816(acc[mt][3], ra[mt], rb[1][1], rb[1][3]);
            }
        }

        // ---- Epilogue: per-(row, subtile) max of m_hat ----
        #pragma unroll
        for (int mt = 0; mt < 4; mt++) {
            float m0 = -INFINITY, m1 = -INFINITY;
            #pragma unroll
            for (int nt = 0; nt < 4; nt++) {
                m0 = fmaxf(m0, fmaxf(acc[mt][nt][0], acc[mt][nt][1]));
                m1 = fmaxf(m1, fmaxf(acc[mt][nt][2], acc[mt][nt][3]));
            }
            m0 = fmaxf(m0, __shfl_xor_sync(0xffffffffu, m0, 1));
            m0 = fmaxf(m0, __shfl_xor_sync(0xffffffffu, m0, 2));
            m1 = fmaxf(m1, __shfl_xor_sync(0xffffffffu, m1, 1));
            m1 = fmaxf(m1, __shfl_xor_sync(0xffffffffu, m1, 2));
            if ((lane & 3) == 0) {
                int rl = wm * 64 + mt * 16 + (lane >> 2);
                stmin[wn * 128 + rl]     = m0;
                stmin[wn * 128 + rl + 8] = m1;
            }
        }
        __syncthreads();
        if (tid < 128) {
            float4 v = make_float4(stmin[tid], stmin[128 + tid],
                                   stmin[256 + tid], stmin[384 + tid]);
            *(float4*)(g_smin + (size_t)(row0 + tid) * 512 + t * 4) = v;
        }
    }
}

// ---------------------------------------------------------------------------
// Exact rescore: warp per row. Scan 512 subtile maxima, flag those within
// MARGIN_M of the row max, exact sequential-fma rescore of all 32 codes in
// each flagged subtile. No overflow mode — exact by construction.
// grid 2048 x 256 (8 warps/block).
// ---------------------------------------------------------------------------
__global__ void k_rescore(const float* __restrict__ z, const float* __restrict__ emb) {
    __shared__ float zs[8][256];
    int wp   = threadIdx.x >> 5;
    int lane = threadIdx.x & 31;
    int w = blockIdx.x * 8 + wp;            // row

    // z row -> smem
    int b = w >> 10, hw = w & 1023;
    const float* zr = z + (size_t)b * CHW + hw;
    #pragma unroll
    for (int c = lane; c < 256; c += 32) zs[wp][c] = zr[(size_t)c * HW];
    __syncwarp();

    // scan subtile maxima
    const float* sm = g_smin + (size_t)w * 512;
    float mv[16];
    float mx = -INFINITY;
    #pragma unroll
    for (int i = 0; i < 16; i++) { mv[i] = sm[i * 32 + lane]; mx = fmaxf(mx, mv[i]); }
    #pragma unroll
    for (int o = 16; o; o >>= 1) mx = fmaxf(mx, __shfl_xor_sync(0xffffffffu, mx, o));
    float thr = mx - MARGIN_M;

    float Sz = g_znorm[w];
    float bestd = INFINITY; int besti = 0x7fffffff;

    #pragma unroll 1
    for (int i = 0; i < 16; i++) {
        unsigned msk = __ballot_sync(0xffffffffu, mv[i] > thr);
        while (msk) {
            int bb = __ffs(msk) - 1;
            msk &= msk - 1;
            int s = i * 32 + bb;
            int code = s * 32 + lane;
            const float* er = emb + (size_t)code * D;
            float a = 0.f;
            #pragma unroll 8
            for (int c = 0; c < D; c++) a = fmaf(zs[wp][c], er[c], a);
            float dd = __fadd_rn(__fadd_rn(Sz, g_enorm[code]), __fmul_rn(-2.0f, a));
            if (dd < bestd || (dd == bestd && code < besti)) { bestd = dd; besti = code; }
        }
    }
    #pragma unroll
    for (int o = 16; o; o >>= 1) {
        float vo = __shfl_xor_sync(0xffffffffu, bestd, o);
        int io = __shfl_xor_sync(0xffffffffu, besti, o);
        if (vo < bestd || (vo == bestd && io < besti)) { bestd = vo; besti = io; }
    }
    if (lane == 0) g_idx[w] = besti;
}

// ---------------------------------------------------------------------------
__global__ void k_finalize(float* __restrict__ out) {
    int r = blockIdx.x * blockDim.x + threadIdx.x;
    if (r >= NROWS) return;
    int idx = g_idx[r];
    out[IDX_OFF + r] = (float)idx;
    out[OH_OFF + (size_t)r * NE + idx] = 1.0f;
    atomicAdd(&g_count[idx], 1);
}

__global__ void k_zq_loss(const float* __restrict__ z, const float* __restrict__ emb,
                          float* __restrict__ out) {
    int t = blockIdx.x * 256 + threadIdx.x;
    int bi = t >> 18;
    int c  = (t >> 10) & 255;
    int hw = t & 1023;
    int row = (bi << 10) + hw;
    int idx = g_idx[row];
    float e  = emb[(size_t)idx * D + c];
    float zp = z[t];
    float diff = __fadd_rn(e, -zp);
    out[ZQ_OFF + (size_t)t] = __fadd_rn(zp, diff);
    __shared__ double sd[256];
    sd[threadIdx.x] = (double)diff * (double)diff;
    __syncthreads();
    #pragma unroll
    for (int s = 128; s > 0; s >>= 1) {
        if (threadIdx.x < s) sd[threadIdx.x] += sd[threadIdx.x + s];
        __syncthreads();
    }
    if (threadIdx.x == 0) g_losspart[blockIdx.x] = sd[0];
}

__global__ void k_loss_final(float* __restrict__ out) {
    __shared__ double sd[1024];
    double s = 0.0;
    for (int i = threadIdx.x; i < 16384; i += 1024) s += g_losspart[i];
    sd[threadIdx.x] = s;
    __syncthreads();
    #pragma unroll
    for (int st = 512; st > 0; st >>= 1) {
        if (threadIdx.x < st) sd[threadIdx.x] += sd[threadIdx.x + st];
        __syncthreads();
    }
    if (threadIdx.x == 0) {
        float m = (float)(sd[0] / 4194304.0);
        out[LOSS_OFF] = __fadd_rn(m, __fmul_rn(0.25f, m));
    }
}

__global__ void k_perp(float* __restrict__ out) {
    __shared__ double sd[1024];
    double s = 0.0;
    for (int j = threadIdx.x; j < NE; j += 1024) {
        float p = (float)g_count[j] * (1.0f / 16384.0f);
        double pd = (double)p;
        s += pd * log(pd + 1e-10);
    }
    sd[threadIdx.x] = s;
    __syncthreads();
    #pragma unroll
    for (int st = 512; st > 0; st >>= 1) {
        if (threadIdx.x < st) sd[threadIdx.x] += sd[threadIdx.x + st];
        __syncthreads();
    }
    if (threadIdx.x == 0) out[PERP_OFF] = (float)exp(-sd[0]);
}

// ---------------------------------------------------------------------------
extern "C" void kernel_launch(void* const* d_in, const int* in_sizes, int n_in,
                              void* d_out, int out_size) {
    const float* z   = (const float*)d_in[0];
    const float* emb = (const float*)d_in[1];
    float* out = (float*)d_out;

    static cudaStream_t s2 = nullptr;
    static cudaEvent_t evF = nullptr, evJ = nullptr;
    if (!s2) {
        cudaFuncSetAttribute(k_main, cudaFuncAttributeMaxDynamicSharedMemorySize, SMEM_BYTES);
        cudaStreamCreateWithFlags(&s2, cudaStreamNonBlocking);
        cudaEventCreateWithFlags(&evF, cudaEventDisableTiming);
        cudaEventCreateWithFlags(&evJ, cudaEventDisableTiming);
    }

    // Fork: 1.07 GB zero-fill runs concurrently with the GEMM pipeline.
    cudaEventRecord(evF, 0);
    cudaStreamWaitEvent(s2, evF, 0);
    k_zero<<<8192, 256, 0, s2>>>(out, (long long)out_size);
    k_zero_counts<<<64, 256, 0, s2>>>();
    cudaEventRecord(evJ, s2);

    k_eprep<<<NE / 32, 256>>>(emb);
    k_znorm<<<NROWS / 256, 256>>>(z);

    k_main<<<128, 256, SMEM_BYTES>>>(z);

    k_rescore<<<NROWS / 8, 256>>>(z, emb);

    cudaStreamWaitEvent(0, evJ, 0);     // join before touching out[OH..]
    k_finalize<<<NROWS / 256, 256>>>(out);
    k_zq_loss<<<(NROWS * D) / 256, 256>>>(z, emb, out);
    k_loss_final<<<1, 1024>>>(out);
    k_perp<<<1, 1024>>>(out);
}

// round 9
// speedup vs baseline: 202.4067x; 2.7222x over previous
#include <cuda_runtime.h>
#include <cuda_bf16.h>
#include <math.h>
#include <stdint.h>

// Problem constants
#define NROWS 16384
#define NE    16384
#define D     256
#define HW    1024
#define CHW   262144

#define NT       128        // number of 128-code tiles
#define MARGIN_M 2e-4f      // margin on m_hat (provable bound ~9.6e-5)

// Output layout (concatenated reference tuple, float32)
#define ZQ_OFF   0ULL
#define LOSS_OFF 4194304ULL
#define PERP_OFF 4194305ULL
#define OH_OFF   4194306ULL
#define IDX_OFF  272629762ULL

// Scratch
__device__ float  g_enorm[NE];
__device__ float  g_znorm[NROWS];
__device__ int    g_idx[NROWS];
__device__ int    g_count[NE];
__device__ double g_losspart[16384];
__device__ unsigned short g_ebf[NE * D];        // bf16 codebook
__device__ float  g_smax[(size_t)NROWS * 2048]; // per-row per-8-code-subtile max(m_hat)

// ---------------------------------------------------------------------------
// Baseline-PTX helpers
// ---------------------------------------------------------------------------
__device__ __forceinline__ uint32_t smem_to_u32(const void* p) {
    uint32_t a;
    asm("{ .reg .u64 t; cvta.to.shared.u64 t, %1; cvt.u32.u64 %0, t; }" : "=r"(a) : "l"(p));
    return a;
}
__device__ __forceinline__ void cp_async16(uint32_t sa, const void* g) {
    asm volatile("cp.async.cg.shared.global [%0], [%1], 16;" :: "r"(sa), "l"(g));
}
#define CP_COMMIT() asm volatile("cp.async.commit_group;" ::: "memory")
#define CP_WAIT(n)  asm volatile("cp.async.wait_group %0;" :: "n"(n) : "memory")

__device__ __forceinline__ void ldm_x4(uint32_t* r, uint32_t addr) {
    asm volatile("ldmatrix.sync.aligned.m8n8.x4.shared.b16 {%0,%1,%2,%3}, [%4];"
                 : "=r"(r[0]), "=r"(r[1]), "=r"(r[2]), "=r"(r[3]) : "r"(addr));
}
__device__ __forceinline__ void mma16816(float* c, const uint32_t* a, uint32_t b0, uint32_t b1) {
    asm volatile("mma.sync.aligned.m16n8k16.row.col.f32.bf16.bf16.f32 "
                 "{%0,%1,%2,%3}, {%4,%5,%6,%7}, {%8,%9}, {%0,%1,%2,%3};"
                 : "+f"(c[0]), "+f"(c[1]), "+f"(c[2]), "+f"(c[3])
                 : "r"(a[0]), "r"(a[1]), "r"(a[2]), "r"(a[3]), "r"(b0), "r"(b1));
}

// ---------------------------------------------------------------------------
// Zero-fill (side stream, overlapped with GEMM)
// ---------------------------------------------------------------------------
__global__ void k_zero(float* __restrict__ out, long long total) {
    float4* o4 = (float4*)(out + LOSS_OFF);
    long long n = total - (long long)LOSS_OFF;
    long long n4 = n / 4;
    long long i = (long long)blockIdx.x * blockDim.x + threadIdx.x;
    long long stride = (long long)gridDim.x * blockDim.x;
    float4 zz = make_float4(0.f, 0.f, 0.f, 0.f);
    for (long long p = i; p < n4; p += stride) o4[p] = zz;
    long long t0 = n4 * 4;
    if (i < n - t0) out[LOSS_OFF + t0 + i] = 0.f;
}

__global__ void k_zero_counts() {
    int i = blockIdx.x * blockDim.x + threadIdx.x;
    if (i < NE) g_count[i] = 0;
}

// ---------------------------------------------------------------------------
// Fused e-prep: bf16 codebook + exact sequential ||e||^2
// ---------------------------------------------------------------------------
__global__ void k_eprep(const float* __restrict__ emb) {
    __shared__ float se[32 * 257];
    int r0 = blockIdx.x * 32;
    int tid = threadIdx.x;
    const float* src = emb + (size_t)r0 * D;
    #pragma unroll
    for (int l = 0; l < 32; l++) {
        int i = l * 256 + tid;
        se[(i >> 8) * 257 + (i & 255)] = src[i];
    }
    __syncthreads();
    #pragma unroll
    for (int l = 0; l < 16; l++) {
        int id = l * 256 + tid;
        int r = id >> 7, c2 = (id & 127) * 2;
        __nv_bfloat16 h0 = __float2bfloat16_rn(se[r * 257 + c2]);
        __nv_bfloat16 h1 = __float2bfloat16_rn(se[r * 257 + c2 + 1]);
        uint32_t w = (uint32_t)*(unsigned short*)&h0 | ((uint32_t)*(unsigned short*)&h1 << 16);
        ((uint32_t*)g_ebf)[(size_t)(r0 + r) * 128 + (id & 127)] = w;
    }
    if (tid < 32) {
        float s = 0.f;
        const float* row = se + tid * 257;
        for (int k = 0; k < D; k++) s = __fadd_rn(s, __fmul_rn(row[k], row[k]));
        g_enorm[r0 + tid] = s;
    }
}

__global__ void k_znorm(const float* __restrict__ z) {
    int r = blockIdx.x * blockDim.x + threadIdx.x;
    if (r >= NROWS) return;
    int b = r >> 10, hw = r & 1023;
    const float* base = z + (size_t)b * CHW + hw;
    float s = 0.f;
    for (int c = 0; c < D; c++) { float v = base[(size_t)c * HW]; s = __fadd_rn(s, __fmul_rn(v, v)); }
    g_znorm[r] = s;
}

// ---------------------------------------------------------------------------
// Main bf16 mma.sync GEMM — single pass; per-(row, 8-code subtile) max(m_hat)
// 128 CTAs x 256 threads (8 warps, 2x4).
// ---------------------------------------------------------------------------
#define PITCH 528
#define A_OFF 0
#define B_OFF 67584
#define B_SZ  67584
#define ST_OFF (B_OFF + 2 * B_SZ)           // 202752: stmax[128][17] floats
#define SMEM_BYTES (ST_OFF + 128 * 17 * 4)  // 211456

__device__ __forceinline__ void load_btile(uint32_t sB, int j0, int tid) {
    #pragma unroll
    for (int l = 0; l < 16; l++) {
        int cid = l * 256 + tid;
        int n   = cid >> 5;
        int c16 = cid & 31;
        cp_async16(sB + (uint32_t)n * PITCH + (uint32_t)c16 * 16,
                   g_ebf + ((size_t)(j0 + n) << 8) + c16 * 8);
    }
}

__launch_bounds__(256, 1)
__global__ void k_main(const float* __restrict__ z) {
    extern __shared__ char smem[];
    uint32_t sbase = smem_to_u32(smem);
    float* stmax = (float*)(smem + ST_OFF);   // [row][16+pad]

    int tid  = threadIdx.x;
    int lane = tid & 31;
    int wid  = tid >> 5;
    int wm = wid >> 2;
    int wn = wid & 3;
    int row0 = blockIdx.x * 128;
    int b0 = row0 >> 10;
    int hw0 = row0 & 1023;

    // ---- Stage A: z -> bf16 smem [m][k] ----
    {
        const float* zb = z + (size_t)b0 * CHW + hw0;
        int m = tid & 127;
        int chalf = (tid >> 7) * 128;
        #pragma unroll 4
        for (int cc = 0; cc < 64; cc++) {
            int c = chalf + cc * 2;
            float v0 = zb[(size_t)c * HW + m];
            float v1 = zb[(size_t)(c + 1) * HW + m];
            __nv_bfloat16 h0 = __float2bfloat16_rn(v0);
            __nv_bfloat16 h1 = __float2bfloat16_rn(v1);
            uint32_t w = (uint32_t)*(unsigned short*)&h0 | ((uint32_t)*(unsigned short*)&h1 << 16);
            *(uint32_t*)(smem + A_OFF + m * PITCH + c * 2) = w;
        }
    }
    load_btile(sbase + B_OFF, 0, tid);
    CP_COMMIT();

    #pragma unroll 1
    for (int t = 0; t < NT; t++) {
        __syncthreads();                     // prior stmax copy done; buf^1 free
        int buf = t & 1;
        if (t + 1 < NT) {
            load_btile(sbase + B_OFF + (uint32_t)(buf ^ 1) * B_SZ, (t + 1) * 128, tid);
            CP_COMMIT();
            CP_WAIT(1);
        } else {
            CP_WAIT(0);
        }
        __syncthreads();                     // tile t visible

        float acc[4][4][4];
        #pragma unroll
        for (int mt = 0; mt < 4; mt++)
            #pragma unroll
            for (int nt = 0; nt < 4; nt++)
                #pragma unroll
                for (int rr = 0; rr < 4; rr++) acc[mt][nt][rr] = 0.f;

        uint32_t aBase = sbase + A_OFF + (uint32_t)(wm * 64 + (lane & 15)) * PITCH + (uint32_t)(lane >> 4) * 16;
        uint32_t bBase = sbase + B_OFF + (uint32_t)buf * B_SZ
                       + (uint32_t)(wn * 32 + (lane & 15)) * PITCH + (uint32_t)(lane >> 4) * 16;

        #pragma unroll
        for (int ks = 0; ks < 16; ks++) {
            uint32_t ra[4][4], rb[2][4];
            #pragma unroll
            for (int mt = 0; mt < 4; mt++)
                ldm_x4(ra[mt], aBase + (uint32_t)mt * (16 * PITCH) + (uint32_t)ks * 32);
            #pragma unroll
            for (int np = 0; np < 2; np++)
                ldm_x4(rb[np], bBase + (uint32_t)np * (16 * PITCH) + (uint32_t)ks * 32);
            #pragma unroll
            for (int mt = 0; mt < 4; mt++) {
                mma16816(acc[mt][0], ra[mt], rb[0][0], rb[0][2]);
                mma16816(acc[mt][1], ra[mt], rb[0][1], rb[0][3]);
                mma16816(acc[mt][2], ra[mt], rb[1][0], rb[1][2]);
                mma16816(acc[mt][3], ra[mt], rb[1][1], rb[1][3]);
            }
        }

        // ---- Epilogue: per-(row, 8-code subtile) max of m_hat ----
        #pragma unroll
        for (int mt = 0; mt < 4; mt++) {
            int rl = wm * 64 + mt * 16 + (lane >> 2);
            #pragma unroll
            for (int nt = 0; nt < 4; nt++) {
                float m0 = fmaxf(acc[mt][nt][0], acc[mt][nt][1]);
                float m1 = fmaxf(acc[mt][nt][2], acc[mt][nt][3]);
                m0 = fmaxf(m0, __shfl_xor_sync(0xffffffffu, m0, 1));
                m0 = fmaxf(m0, __shfl_xor_sync(0xffffffffu, m0, 2));
                m1 = fmaxf(m1, __shfl_xor_sync(0xffffffffu, m1, 1));
                m1 = fmaxf(m1, __shfl_xor_sync(0xffffffffu, m1, 2));
                if ((lane & 3) == 0) {
                    stmax[rl * 17 + wn * 4 + nt]       = m0;
                    stmax[(rl + 8) * 17 + wn * 4 + nt] = m1;
                }
            }
        }
        __syncthreads();
        if (tid < 128) {
            float* dst = g_smax + (size_t)(row0 + tid) * 2048 + t * 16;
            const float* srcr = stmax + tid * 17;
            #pragma unroll
            for (int q = 0; q < 4; q++) {
                float4 v = make_float4(srcr[q * 4], srcr[q * 4 + 1],
                                       srcr[q * 4 + 2], srcr[q * 4 + 3]);
                *(float4*)(dst + q * 4) = v;
            }
        }
    }
}

// ---------------------------------------------------------------------------
// Exact rescore: warp per row. Scan 2048 subtile-8 maxima, flag within
// MARGIN_M of the row max; exact sequential-fma chain (float4 loads) on the
// 8 codes of each flagged subtile. 4 warps/block, grid NROWS/4.
// ---------------------------------------------------------------------------
__global__ void k_rescore(const float* __restrict__ z, const float* __restrict__ emb) {
    __shared__ float zs[4][256];
    __shared__ int flist[4][64];
    __shared__ int fcnt[4];
    int wp   = threadIdx.x >> 5;
    int lane = threadIdx.x & 31;
    int w = blockIdx.x * 4 + wp;

    // z row -> smem
    int b = w >> 10, hw = w & 1023;
    const float* zr = z + (size_t)b * CHW + hw;
    #pragma unroll
    for (int c = lane; c < 256; c += 32) zs[wp][c] = zr[(size_t)c * HW];
    if (lane == 0) fcnt[wp] = 0;
    __syncwarp();

    // global max of subtile maxima
    const float4* sm4 = (const float4*)(g_smax + (size_t)w * 2048);
    float mx = -INFINITY;
    #pragma unroll
    for (int i = 0; i < 16; i++) {
        float4 v = sm4[i * 32 + lane];
        mx = fmaxf(mx, fmaxf(fmaxf(v.x, v.y), fmaxf(v.z, v.w)));
    }
    #pragma unroll
    for (int o = 16; o; o >>= 1) mx = fmaxf(mx, __shfl_xor_sync(0xffffffffu, mx, o));
    float thr = mx - MARGIN_M;

    // collect flagged subtiles
    #pragma unroll
    for (int i = 0; i < 16; i++) {
        float4 v = sm4[i * 32 + lane];
        int sb = (i * 32 + lane) * 4;
        if (v.x > thr) { int p = atomicAdd(&fcnt[wp], 1); if (p < 64) flist[wp][p] = sb; }
        if (v.y > thr) { int p = atomicAdd(&fcnt[wp], 1); if (p < 64) flist[wp][p] = sb + 1; }
        if (v.z > thr) { int p = atomicAdd(&fcnt[wp], 1); if (p < 64) flist[wp][p] = sb + 2; }
        if (v.w > thr) { int p = atomicAdd(&fcnt[wp], 1); if (p < 64) flist[wp][p] = sb + 3; }
    }
    __syncwarp();
    int nf = fcnt[wp];

    float Sz = g_znorm[w];
    float bestd = INFINITY; int besti = 0x7fffffff;

    if (nf <= 64) {
        for (int base = 0; base < nf; base += 4) {
            int li = base + (lane >> 3);
            float dd = INFINITY; int code = 0x7fffffff;
            if (li < nf) {
                int s = flist[wp][li];
                code = s * 8 + (lane & 7);
                const float4* er = (const float4*)(emb + (size_t)code * D);
                float a = 0.f;
                #pragma unroll 16
                for (int q = 0; q < 64; q++) {
                    float4 ev = er[q];
                    a = fmaf(zs[wp][q * 4],     ev.x, a);
                    a = fmaf(zs[wp][q * 4 + 1], ev.y, a);
                    a = fmaf(zs[wp][q * 4 + 2], ev.z, a);
                    a = fmaf(zs[wp][q * 4 + 3], ev.w, a);
                }
                dd = __fadd_rn(__fadd_rn(Sz, g_enorm[code]), __fmul_rn(-2.0f, a));
            }
            if (dd < bestd || (dd == bestd && code < besti)) { bestd = dd; besti = code; }
        }
    } else {
        // overflow (effectively impossible): exact streaming scan of all subtiles
        const float* sm = g_smax + (size_t)w * 2048;
        for (int sb = 0; sb < 2048; sb += 4) {
            int s = sb + (lane >> 3);
            float dd = INFINITY; int code = 0x7fffffff;
            if (sm[s] > thr) {
                code = s * 8 + (lane & 7);
                const float4* er = (const float4*)(emb + (size_t)code * D);
                float a = 0.f;
                for (int q = 0; q < 64; q++) {
                    float4 ev = er[q];
                    a = fmaf(zs[wp][q * 4],     ev.x, a);
                    a = fmaf(zs[wp][q * 4 + 1], ev.y, a);
                    a = fmaf(zs[wp][q * 4 + 2], ev.z, a);
                    a = fmaf(zs[wp][q * 4 + 3], ev.w, a);
                }
                dd = __fadd_rn(__fadd_rn(Sz, g_enorm[code]), __fmul_rn(-2.0f, a));
            }
            if (dd < bestd || (dd == bestd && code < besti)) { bestd = dd; besti = code; }
        }
    }
    #pragma unroll
    for (int o = 16; o; o >>= 1) {
        float vo = __shfl_xor_sync(0xffffffffu, bestd, o);
        int io = __shfl_xor_sync(0xffffffffu, besti, o);
        if (vo < bestd || (vo == bestd && io < besti)) { bestd = vo; besti = io; }
    }
    if (lane == 0) g_idx[w] = besti;
}

// ---------------------------------------------------------------------------
__global__ void k_finalize(float* __restrict__ out) {
    int r = blockIdx.x * blockDim.x + threadIdx.x;
    if (r >= NROWS) return;
    int idx = g_idx[r];
    out[IDX_OFF + r] = (float)idx;
    out[OH_OFF + (size_t)r * NE + idx] = 1.0f;
    atomicAdd(&g_count[idx], 1);
}

__global__ void k_zq_loss(const float* __restrict__ z, const float* __restrict__ emb,
                          float* __restrict__ out) {
    int t = blockIdx.x * 256 + threadIdx.x;
    int bi = t >> 18;
    int c  = (t >> 10) & 255;
    int hw = t & 1023;
    int row = (bi << 10) + hw;
    int idx = g_idx[row];
    float e  = emb[(size_t)idx * D + c];
    float zp = z[t];
    float diff = __fadd_rn(e, -zp);
    out[ZQ_OFF + (size_t)t] = __fadd_rn(zp, diff);
    __shared__ double sd[256];
    sd[threadIdx.x] = (double)diff * (double)diff;
    __syncthreads();
    #pragma unroll
    for (int s = 128; s > 0; s >>= 1) {
        if (threadIdx.x < s) sd[threadIdx.x] += sd[threadIdx.x + s];
        __syncthreads();
    }
    if (threadIdx.x == 0) g_losspart[blockIdx.x] = sd[0];
}

__global__ void k_loss_final(float* __restrict__ out) {
    __shared__ double sd[1024];
    double s = 0.0;
    for (int i = threadIdx.x; i < 16384; i += 1024) s += g_losspart[i];
    sd[threadIdx.x] = s;
    __syncthreads();
    #pragma unroll
    for (int st = 512; st > 0; st >>= 1) {
        if (threadIdx.x < st) sd[threadIdx.x] += sd[threadIdx.x + st];
        __syncthreads();
    }
    if (threadIdx.x == 0) {
        float m = (float)(sd[0] / 4194304.0);
        out[LOSS_OFF] = __fadd_rn(m, __fmul_rn(0.25f, m));
    }
}

__global__ void k_perp(float* __restrict__ out) {
    __shared__ double sd[1024];
    double s = 0.0;
    for (int j = threadIdx.x; j < NE; j += 1024) {
        float p = (float)g_count[j] * (1.0f / 16384.0f);
        double pd = (double)p;
        s += pd * log(pd + 1e-10);
    }
    sd[threadIdx.x] = s;
    __syncthreads();
    #pragma unroll
    for (int st = 512; st > 0; st >>= 1) {
        if (threadIdx.x < st) sd[threadIdx.x] += sd[threadIdx.x + st];
        __syncthreads();
    }
    if (threadIdx.x == 0) out[PERP_OFF] = (float)exp(-sd[0]);
}

// ---------------------------------------------------------------------------
extern "C" void kernel_launch(void* const* d_in, const int* in_sizes, int n_in,
                              void* d_out, int out_size) {
    const float* z   = (const float*)d_in[0];
    const float* emb = (const float*)d_in[1];
    float* out = (float*)d_out;

    static cudaStream_t s2 = nullptr;
    static cudaEvent_t evF = nullptr, evJ = nullptr;
    if (!s2) {
        cudaFuncSetAttribute(k_main, cudaFuncAttributeMaxDynamicSharedMemorySize, SMEM_BYTES);
        cudaStreamCreateWithFlags(&s2, cudaStreamNonBlocking);
        cudaEventCreateWithFlags(&evF, cudaEventDisableTiming);
        cudaEventCreateWithFlags(&evJ, cudaEventDisableTiming);
    }

    // Fork: 1.07 GB zero-fill runs concurrently with the GEMM pipeline.
    cudaEventRecord(evF, 0);
    cudaStreamWaitEvent(s2, evF, 0);
    k_zero<<<8192, 256, 0, s2>>>(out, (long long)out_size);
    k_zero_counts<<<64, 256, 0, s2>>>();
    cudaEventRecord(evJ, s2);

    k_eprep<<<NE / 32, 256>>>(emb);
    k_znorm<<<NROWS / 256, 256>>>(z);

    k_main<<<128, 256, SMEM_BYTES>>>(z);

    k_rescore<<<NROWS / 4, 128>>>(z, emb);

    cudaStreamWaitEvent(0, evJ, 0);     // join before touching out[OH..]
    k_finalize<<<NROWS / 256, 256>>>(out);
    k_zq_loss<<<(NROWS * D) / 256, 256>>>(z, emb, out);
    k_loss_final<<<1, 1024>>>(out);
    k_perp<<<1, 1024>>>(out);
}

// round 10
// speedup vs baseline: 218.5139x; 1.0796x over previous
#include <cuda_runtime.h>
#include <cuda_bf16.h>
#include <math.h>
#include <stdint.h>

// Problem constants
#define NROWS 16384
#define NE    16384
#define D     256
#define HW    1024
#define CHW   262144

#define NT       128        // number of 128-code tiles
#define MARGIN_M 2e-4f      // margin on m_hat (provable bound ~9.6e-5)

// Output layout (concatenated reference tuple, float32)
#define ZQ_OFF   0ULL
#define LOSS_OFF 4194304ULL
#define PERP_OFF 4194305ULL
#define OH_OFF   4194306ULL
#define IDX_OFF  272629762ULL

// Scratch
__device__ float  g_enorm[NE];
__device__ float  g_znorm[NROWS];
__device__ int    g_idx[NROWS];
__device__ int    g_count[NE];
__device__ double g_losspart[16384];
__device__ uint4  g_ebf8[NE * 32];              // bf16 codebook, tile-major + swizzled (8 MB)
__device__ float  g_smax[(size_t)NROWS * 2048]; // per-row per-8-code-subtile max(m_hat)

// ---------------------------------------------------------------------------
// Baseline-PTX helpers (sm_90 features only — no `a`-suffix instructions)
// ---------------------------------------------------------------------------
__device__ __forceinline__ uint32_t smem_to_u32(const void* p) {
    uint32_t a;
    asm("{ .reg .u64 t; cvta.to.shared.u64 t, %1; cvt.u32.u64 %0, t; }" : "=r"(a) : "l"(p));
    return a;
}
#define MBARRIER_INIT(mb, cnt) \
    asm volatile("mbarrier.init.shared.b64 [%0], %1;" :: "r"((uint32_t)(mb)), "r"((uint32_t)(cnt)) : "memory")
#define MBARRIER_EXPECT_TX(mb, bytes) \
    asm volatile("mbarrier.arrive.expect_tx.shared.b64 _, [%0], %1;" :: "r"((uint32_t)(mb)), "r"((uint32_t)(bytes)) : "memory")
#define MBARRIER_WAIT_PARITY(mb, ph) do {                                          \
    uint32_t _m = (uint32_t)(mb); uint32_t _p = (uint32_t)(ph); uint32_t _d;       \
    asm volatile("{\n\t.reg .pred p;\n\t"                                          \
        "mbarrier.try_wait.parity.shared.b64 p, [%1], %2;\n\t"                     \
        "selp.b32 %0, 1, 0, p;\n\t}" : "=r"(_d) : "r"(_m), "r"(_p) : "memory");    \
    if (!_d) {                                                                     \
        asm volatile("{\n\t.reg .pred P1;\n\tWL_%=:\n\t"                           \
            "mbarrier.try_wait.parity.shared.b64 P1, [%0], %1;\n\t"                \
            "@P1 bra.uni WD_%=;\n\tbra.uni WL_%=;\n\tWD_%=:\n\t}"                  \
            :: "r"(_m), "r"(_p) : "memory");                                       \
    } } while (0)

__device__ __forceinline__ void bulk_g2s(uint32_t dst, const void* src, uint32_t bytes, uint32_t mbar) {
    asm volatile("cp.async.bulk.shared::cluster.global.mbarrier::complete_tx::bytes [%0], [%1], %2, [%3];"
                 :: "r"(dst), "l"(src), "r"(bytes), "r"(mbar) : "memory");
}

__device__ __forceinline__ void ldm_x4(uint32_t* r, uint32_t addr) {
    asm volatile("ldmatrix.sync.aligned.m8n8.x4.shared.b16 {%0,%1,%2,%3}, [%4];"
                 : "=r"(r[0]), "=r"(r[1]), "=r"(r[2]), "=r"(r[3]) : "r"(addr));
}
__device__ __forceinline__ void mma16816(float* c, const uint32_t* a, uint32_t b0, uint32_t b1) {
    asm volatile("mma.sync.aligned.m16n8k16.row.col.f32.bf16.bf16.f32 "
                 "{%0,%1,%2,%3}, {%4,%5,%6,%7}, {%8,%9}, {%0,%1,%2,%3};"
                 : "+f"(c[0]), "+f"(c[1]), "+f"(c[2]), "+f"(c[3])
                 : "r"(a[0]), "r"(a[1]), "r"(a[2]), "r"(a[3]), "r"(b0), "r"(b1));
}

// ---------------------------------------------------------------------------
// Zero-fill (side stream, overlapped with GEMM)
// ---------------------------------------------------------------------------
__global__ void k_zero(float* __restrict__ out, long long total) {
    float4* o4 = (float4*)(out + LOSS_OFF);
    long long n = total - (long long)LOSS_OFF;
    long long n4 = n / 4;
    long long i = (long long)blockIdx.x * blockDim.x + threadIdx.x;
    long long stride = (long long)gridDim.x * blockDim.x;
    float4 zz = make_float4(0.f, 0.f, 0.f, 0.f);
    for (long long p = i; p < n4; p += stride) o4[p] = zz;
    long long t0 = n4 * 4;
    if (i < n - t0) out[LOSS_OFF + t0 + i] = 0.f;
}

__global__ void k_zero_counts() {
    int i = blockIdx.x * blockDim.x + threadIdx.x;
    if (i < NE) g_count[i] = 0;
}

// ---------------------------------------------------------------------------
// Fused e-prep: exact sequential ||e||^2 + bf16 codebook in TILE-MAJOR
// SWIZZLED layout: tile t (codes t*128..+127) occupies uint4 block
// g_ebf8[t*4096 .. +4096); code n (local), 16B chunk c (8 bf16 dims) at
// index t*4096 + n*32 + (c ^ (n&7)).
// 512 blocks x 256 threads, 32 rows per block.
// ---------------------------------------------------------------------------
__global__ void k_eprep(const float* __restrict__ emb) {
    __shared__ float se[32 * 257];
    int r0 = blockIdx.x * 32;
    int tid = threadIdx.x;
    const float* src = emb + (size_t)r0 * D;
    #pragma unroll
    for (int l = 0; l < 32; l++) {
        int i = l * 256 + tid;
        se[(i >> 8) * 257 + (i & 255)] = src[i];
    }
    __syncthreads();
    #pragma unroll
    for (int l = 0; l < 4; l++) {
        int id = l * 256 + tid;              // chunk id: 32 rows x 32 chunks
        int r = id >> 5, c = id & 31;
        int j = r0 + r;
        int tile = j >> 7, n = j & 127;
        const float* s8 = se + r * 257 + c * 8;
        uint32_t w[4];
        #pragma unroll
        for (int q = 0; q < 4; q++) {
            __nv_bfloat16 h0 = __float2bfloat16_rn(s8[q * 2]);
            __nv_bfloat16 h1 = __float2bfloat16_rn(s8[q * 2 + 1]);
            w[q] = (uint32_t)*(unsigned short*)&h0 | ((uint32_t)*(unsigned short*)&h1 << 16);
        }
        g_ebf8[(size_t)tile * 4096 + n * 32 + (c ^ (n & 7))] =
            make_uint4(w[0], w[1], w[2], w[3]);
    }
    if (tid < 32) {
        float s = 0.f;
        const float* row = se + tid * 257;
        for (int k = 0; k < D; k++) s = __fadd_rn(s, __fmul_rn(row[k], row[k]));
        g_enorm[r0 + tid] = s;
    }
}

__global__ void k_znorm(const float* __restrict__ z) {
    int r = blockIdx.x * blockDim.x + threadIdx.x;
    if (r >= NROWS) return;
    int b = r >> 10, hw = r & 1023;
    const float* base = z + (size_t)b * CHW + hw;
    float s = 0.f;
    for (int c = 0; c < D; c++) { float v = base[(size_t)c * HW]; s = __fadd_rn(s, __fmul_rn(v, v)); }
    g_znorm[r] = s;
}

// ---------------------------------------------------------------------------
// Main bf16 mma.sync GEMM — single pass, cp.async.bulk double buffer.
// smem rows are 512B, XOR-swizzled at 16B: chunk c of row r at c^(r&7).
// 128 CTAs x 256 threads (8 warps, 2x4).
// ---------------------------------------------------------------------------
#define A_OFF 0
#define B_OFF 65536
#define B_SZ  65536
#define ST_OFF (B_OFF + 2 * B_SZ)           // 196608: stmax[128][17] floats
#define MB_OFF (ST_OFF + 128 * 17 * 4)      // 205312: two mbarriers
#define SMEM_BYTES (MB_OFF + 32)            // 205344

__launch_bounds__(256, 1)
__global__ void k_main(const float* __restrict__ z) {
    extern __shared__ char smem[];
    uint32_t sbase = smem_to_u32(smem);
    float* stmax = (float*)(smem + ST_OFF);
    uint32_t mb0 = sbase + MB_OFF, mb1 = sbase + MB_OFF + 8;

    int tid  = threadIdx.x;
    int lane = tid & 31;
    int wid  = tid >> 5;
    int wm = wid >> 2;
    int wn = wid & 3;
    int row0 = blockIdx.x * 128;
    int b0 = row0 >> 10;
    int hw0 = row0 & 1023;

    if (tid == 0) { MBARRIER_INIT(mb0, 1); MBARRIER_INIT(mb1, 1); }
    __syncthreads();
    if (tid == 0) {
        MBARRIER_EXPECT_TX(mb0, B_SZ);
        bulk_g2s(sbase + B_OFF, g_ebf8, B_SZ, mb0);
        MBARRIER_EXPECT_TX(mb1, B_SZ);
        bulk_g2s(sbase + B_OFF + B_SZ, g_ebf8 + 4096, B_SZ, mb1);
    }

    // ---- Stage A: z -> bf16 smem, 512B rows, swizzled 16B chunks ----
    {
        const float* zb = z + (size_t)b0 * CHW + hw0;
        int m = tid & 127;
        int cbase = (tid >> 7) * 16;
        int mx7 = m & 7;
        #pragma unroll 2
        for (int cc = 0; cc < 16; cc++) {
            int c = cbase + cc;              // 16B chunk = dims c*8..c*8+7
            uint32_t w[4];
            #pragma unroll
            for (int q = 0; q < 4; q++) {
                float v0 = zb[(size_t)(c * 8 + q * 2)     * HW + m];
                float v1 = zb[(size_t)(c * 8 + q * 2 + 1) * HW + m];
                __nv_bfloat16 h0 = __float2bfloat16_rn(v0);
                __nv_bfloat16 h1 = __float2bfloat16_rn(v1);
                w[q] = (uint32_t)*(unsigned short*)&h0 | ((uint32_t)*(unsigned short*)&h1 << 16);
            }
            *(uint4*)(smem + A_OFF + m * 512 + ((c ^ mx7) << 4)) =
                make_uint4(w[0], w[1], w[2], w[3]);
        }
    }
    __syncthreads();                         // A visible to all warps

    #pragma unroll 1
    for (int t = 0; t < NT; t++) {
        int buf = t & 1;
        MBARRIER_WAIT_PARITY(buf ? mb1 : mb0, (t >> 1) & 1);

        float acc[4][4][4];
        #pragma unroll
        for (int mt = 0; mt < 4; mt++)
            #pragma unroll
            for (int nt = 0; nt < 4; nt++)
                #pragma unroll
                for (int rr = 0; rr < 4; rr++) acc[mt][nt][rr] = 0.f;

        int rA = wm * 64 + (lane & 15);          // + mt*16
        int rB = wn * 32 + (lane & 15);          // + np*16
        int hi = lane >> 4;
        uint32_t bB = sbase + B_OFF + (uint32_t)buf * B_SZ;

        #pragma unroll
        for (int ks = 0; ks < 16; ks++) {
            int chunk = ks * 2 + hi;
            uint32_t ra[4][4], rb[2][4];
            #pragma unroll
            for (int mt = 0; mt < 4; mt++) {
                int r = rA + mt * 16;
                ldm_x4(ra[mt], sbase + A_OFF + (uint32_t)(r * 512 + ((chunk ^ (r & 7)) << 4)));
            }
            #pragma unroll
            for (int np = 0; np < 2; np++) {
                int r = rB + np * 16;
                ldm_x4(rb[np], bB + (uint32_t)(r * 512 + ((chunk ^ (r & 7)) << 4)));
            }
            #pragma unroll
            for (int mt = 0; mt < 4; mt++) {
                mma16816(acc[mt][0], ra[mt], rb[0][0], rb[0][2]);
                mma16816(acc[mt][1], ra[mt], rb[0][1], rb[0][3]);
                mma16816(acc[mt][2], ra[mt], rb[1][0], rb[1][2]);
                mma16816(acc[mt][3], ra[mt], rb[1][1], rb[1][3]);
            }
        }

        // ---- Epilogue: per-(row, 8-code subtile) max of m_hat ----
        #pragma unroll
        for (int mt = 0; mt < 4; mt++) {
            int rl = wm * 64 + mt * 16 + (lane >> 2);
            #pragma unroll
            for (int nt = 0; nt < 4; nt++) {
                float m0 = fmaxf(acc[mt][nt][0], acc[mt][nt][1]);
                float m1 = fmaxf(acc[mt][nt][2], acc[mt][nt][3]);
                m0 = fmaxf(m0, __shfl_xor_sync(0xffffffffu, m0, 1));
                m0 = fmaxf(m0, __shfl_xor_sync(0xffffffffu, m0, 2));
                m1 = fmaxf(m1, __shfl_xor_sync(0xffffffffu, m1, 1));
                m1 = fmaxf(m1, __shfl_xor_sync(0xffffffffu, m1, 2));
                if ((lane & 3) == 0) {
                    stmax[rl * 17 + wn * 4 + nt]       = m0;
                    stmax[(rl + 8) * 17 + wn * 4 + nt] = m1;
                }
            }
        }
        __syncthreads();
        if (tid < 128) {
            float* dst = g_smax + (size_t)(row0 + tid) * 2048 + t * 16;
            const float* srcr = stmax + tid * 17;
            #pragma unroll
            for (int q = 0; q < 4; q++)
                *(float4*)(dst + q * 4) = make_float4(srcr[q * 4], srcr[q * 4 + 1],
                                                      srcr[q * 4 + 2], srcr[q * 4 + 3]);
        }
        __syncthreads();                     // buf fully consumed; stmax free
        if (t + 2 < NT && tid == 0) {
            uint32_t mb = buf ? mb1 : mb0;
            MBARRIER_EXPECT_TX(mb, B_SZ);
            bulk_g2s(sbase + B_OFF + (uint32_t)buf * B_SZ,
                     g_ebf8 + (size_t)(t + 2) * 4096, B_SZ, mb);
        }
    }
}

// ---------------------------------------------------------------------------
// Exact rescore: warp per row. Scan 2048 subtile-8 maxima, flag within
// MARGIN_M of the row max; exact sequential-fma chain (float4 loads) on the
// 8 codes of each flagged subtile.
// ---------------------------------------------------------------------------
__global__ void k_rescore(const float* __restrict__ z, const float* __restrict__ emb) {
    __shared__ float zs[4][256];
    __shared__ int flist[4][64];
    __shared__ int fcnt[4];
    int wp   = threadIdx.x >> 5;
    int lane = threadIdx.x & 31;
    int w = blockIdx.x * 4 + wp;

    int b = w >> 10, hw = w & 1023;
    const float* zr = z + (size_t)b * CHW + hw;
    #pragma unroll
    for (int c = lane; c < 256; c += 32) zs[wp][c] = zr[(size_t)c * HW];
    if (lane == 0) fcnt[wp] = 0;
    __syncwarp();

    const float4* sm4 = (const float4*)(g_smax + (size_t)w * 2048);
    float mx = -INFINITY;
    #pragma unroll
    for (int i = 0; i < 16; i++) {
        float4 v = sm4[i * 32 + lane];
        mx = fmaxf(mx, fmaxf(fmaxf(v.x, v.y), fmaxf(v.z, v.w)));
    }
    #pragma unroll
    for (int o = 16; o; o >>= 1) mx = fmaxf(mx, __shfl_xor_sync(0xffffffffu, mx, o));
    float thr = mx - MARGIN_M;

    #pragma unroll
    for (int i = 0; i < 16; i++) {
        float4 v = sm4[i * 32 + lane];
        int sb = (i * 32 + lane) * 4;
        if (v.x > thr) { int p = atomicAdd(&fcnt[wp], 1); if (p < 64) flist[wp][p] = sb; }
        if (v.y > thr) { int p = atomicAdd(&fcnt[wp], 1); if (p < 64) flist[wp][p] = sb + 1; }
        if (v.z > thr) { int p = atomicAdd(&fcnt[wp], 1); if (p < 64) flist[wp][p] = sb + 2; }
        if (v.w > thr) { int p = atomicAdd(&fcnt[wp], 1); if (p < 64) flist[wp][p] = sb + 3; }
    }
    __syncwarp();
    int nf = fcnt[wp];

    float Sz = g_znorm[w];
    float bestd = INFINITY; int besti = 0x7fffffff;

    if (nf <= 64) {
        for (int base = 0; base < nf; base += 4) {
            int li = base + (lane >> 3);
            float dd = INFINITY; int code = 0x7fffffff;
            if (li < nf) {
                int s = flist[wp][li];
                code = s * 8 + (lane & 7);
                const float4* er = (const float4*)(emb + (size_t)code * D);
                float a = 0.f;
                #pragma unroll 16
                for (int q = 0; q < 64; q++) {
                    float4 ev = er[q];
                    a = fmaf(zs[wp][q * 4],     ev.x, a);
                    a = fmaf(zs[wp][q * 4 + 1], ev.y, a);
                    a = fmaf(zs[wp][q * 4 + 2], ev.z, a);
                    a = fmaf(zs[wp][q * 4 + 3], ev.w, a);
                }
                dd = __fadd_rn(__fadd_rn(Sz, g_enorm[code]), __fmul_rn(-2.0f, a));
            }
            if (dd < bestd || (dd == bestd && code < besti)) { bestd = dd; besti = code; }
        }
    } else {
        const float* sm = g_smax + (size_t)w * 2048;
        for (int sb = 0; sb < 2048; sb += 4) {
            int s = sb + (lane >> 3);
            float dd = INFINITY; int code = 0x7fffffff;
            if (sm[s] > thr) {
                code = s * 8 + (lane & 7);
                const float4* er = (const float4*)(emb + (size_t)code * D);
                float a = 0.f;
                for (int q = 0; q < 64; q++) {
                    float4 ev = er[q];
                    a = fmaf(zs[wp][q * 4],     ev.x, a);
                    a = fmaf(zs[wp][q * 4 + 1], ev.y, a);
                    a = fmaf(zs[wp][q * 4 + 2], ev.z, a);
                    a = fmaf(zs[wp][q * 4 + 3], ev.w, a);
                }
                dd = __fadd_rn(__fadd_rn(Sz, g_enorm[code]), __fmul_rn(-2.0f, a));
            }
            if (dd < bestd || (dd == bestd && code < besti)) { bestd = dd; besti = code; }
        }
    }
    #pragma unroll
    for (int o = 16; o; o >>= 1) {
        float vo = __shfl_xor_sync(0xffffffffu, bestd, o);
        int io = __shfl_xor_sync(0xffffffffu, besti, o);
        if (vo < bestd || (vo == bestd && io < besti)) { bestd = vo; besti = io; }
    }
    if (lane == 0) g_idx[w] = besti;
}

// ---------------------------------------------------------------------------
__global__ void k_finalize(float* __restrict__ out) {
    int r = blockIdx.x * blockDim.x + threadIdx.x;
    if (r >= NROWS) return;
    int idx = g_idx[r];
    out[IDX_OFF + r] = (float)idx;
    out[OH_OFF + (size_t)r * NE + idx] = 1.0f;
    atomicAdd(&g_count[idx], 1);
}

__global__ void k_zq_loss(const float* __restrict__ z, const float* __restrict__ emb,
                          float* __restrict__ out) {
    int t = blockIdx.x * 256 + threadIdx.x;
    int bi = t >> 18;
    int c  = (t >> 10) & 255;
    int hw = t & 1023;
    int row = (bi << 10) + hw;
    int idx = g_idx[row];
    float e  = emb[(size_t)idx * D + c];
    float zp = z[t];
    float diff = __fadd_rn(e, -zp);
    out[ZQ_OFF + (size_t)t] = __fadd_rn(zp, diff);
    __shared__ double sd[256];
    sd[threadIdx.x] = (double)diff * (double)diff;
    __syncthreads();
    #pragma unroll
    for (int s = 128; s > 0; s >>= 1) {
        if (threadIdx.x < s) sd[threadIdx.x] += sd[threadIdx.x + s];
        __syncthreads();
    }
    if (threadIdx.x == 0) g_losspart[blockIdx.x] = sd[0];
}

__global__ void k_loss_final(float* __restrict__ out) {
    __shared__ double sd[1024];
    double s = 0.0;
    for (int i = threadIdx.x; i < 16384; i += 1024) s += g_losspart[i];
    sd[threadIdx.x] = s;
    __syncthreads();
    #pragma unroll
    for (int st = 512; st > 0; st >>= 1) {
        if (threadIdx.x < st) sd[threadIdx.x] += sd[threadIdx.x + st];
        __syncthreads();
    }
    if (threadIdx.x == 0) {
        float m = (float)(sd[0] / 4194304.0);
        out[LOSS_OFF] = __fadd_rn(m, __fmul_rn(0.25f, m));
    }
}

__global__ void k_perp(float* __restrict__ out) {
    __shared__ double sd[1024];
    double s = 0.0;
    for (int j = threadIdx.x; j < NE; j += 1024) {
        float p = (float)g_count[j] * (1.0f / 16384.0f);
        double pd = (double)p;
        s += pd * log(pd + 1e-10);
    }
    sd[threadIdx.x] = s;
    __syncthreads();
    #pragma unroll
    for (int st = 512; st > 0; st >>= 1) {
        if (threadIdx.x < st) sd[threadIdx.x] += sd[threadIdx.x + st];
        __syncthreads();
    }
    if (threadIdx.x == 0) out[PERP_OFF] = (float)exp(-sd[0]);
}

// ---------------------------------------------------------------------------
extern "C" void kernel_launch(void* const* d_in, const int* in_sizes, int n_in,
                              void* d_out, int out_size) {
    const float* z   = (const float*)d_in[0];
    const float* emb = (const float*)d_in[1];
    float* out = (float*)d_out;

    static cudaStream_t s2 = nullptr;
    static cudaEvent_t evF = nullptr, evJ = nullptr;
    if (!s2) {
        cudaFuncSetAttribute(k_main, cudaFuncAttributeMaxDynamicSharedMemorySize, SMEM_BYTES);
        cudaStreamCreateWithFlags(&s2, cudaStreamNonBlocking);
        cudaEventCreateWithFlags(&evF, cudaEventDisableTiming);
        cudaEventCreateWithFlags(&evJ, cudaEventDisableTiming);
    }

    // Fork: 1.07 GB zero-fill runs concurrently with the GEMM pipeline.
    cudaEventRecord(evF, 0);
    cudaStreamWaitEvent(s2, evF, 0);
    k_zero<<<8192, 256, 0, s2>>>(out, (long long)out_size);
    k_zero_counts<<<64, 256, 0, s2>>>();
    cudaEventRecord(evJ, s2);

    k_eprep<<<NE / 32, 256>>>(emb);
    k_znorm<<<NROWS / 256, 256>>>(z);

    k_main<<<128, 256, SMEM_BYTES>>>(z);

    k_rescore<<<NROWS / 4, 128>>>(z, emb);

    cudaStreamWaitEvent(0, evJ, 0);     // join before touching out[OH..]
    k_finalize<<<NROWS / 256, 256>>>(out);
    k_zq_loss<<<(NROWS * D) / 256, 256>>>(z, emb, out);
    k_loss_final<<<1, 1024>>>(out);
    k_perp<<<1, 1024>>>(out);
}